// round 2
// baseline (speedup 1.0000x reference)
#include <cuda_runtime.h>
#include <math.h>

#define N_NODES 24576
#define B_GRAPHS 128
#define D_IN     92
#define DMODEL   512
#define NHEAD    8
#define HDIM     64
#define NLAYER   3
#define DFF      2048
#define MAX_CNT  512   // safe bound on nodes per graph (mean 192, sd ~14)

// ---------------- device scratch (no allocations allowed) ----------------
__device__ float g_h   [(size_t)N_NODES * DMODEL];      // hidden state
__device__ float g_qkv [(size_t)N_NODES * 3 * DMODEL];  // fused qkv
__device__ float g_o   [(size_t)N_NODES * DMODEL];      // attn concat out
__device__ float g_x   [(size_t)N_NODES * DMODEL];      // post-attn residual
__device__ float g_f   [(size_t)N_NODES * DFF];         // ffn intermediate
__device__ float g_pool[B_GRAPHS * DMODEL];
__device__ float g_ph  [B_GRAPHS * DMODEL];
__device__ int   g_counts[B_GRAPHS];
__device__ int   g_starts[B_GRAPHS];

// ---------------- graph metadata ----------------
// batch is int32 on device (JAX x64 disabled downcasts jnp.int64 -> int32)
__global__ void count_kernel(const int* __restrict__ batch) {
    int i = blockIdx.x * blockDim.x + threadIdx.x;
    if (i < N_NODES) {
        int g = batch[i];
        if (g >= 0 && g < B_GRAPHS) atomicAdd(&g_counts[g], 1);
    }
}

__global__ void scan_kernel() {
    // single thread exclusive scan over 128 graphs
    int s = 0;
    for (int g = 0; g < B_GRAPHS; g++) {
        g_starts[g] = s;
        s += g_counts[g];
    }
}

// ---------------- generic SGEMM:  C = A @ W^T + bias (+res) (+act) ----------------
// A: M x K row-major, W: N x K row-major, C: M x N row-major.
// M % 128 == 0, N % 128 == 0 required (holds for all call sites). K arbitrary.
// ACT: 0 none, 1 relu, 2 silu
template <int ACT>
__global__ void __launch_bounds__(256, 2)
sgemm_kernel(const float* __restrict__ A, const float* __restrict__ W,
             const float* __restrict__ bias, const float* __restrict__ res,
             float* __restrict__ C, int M, int N, int K)
{
    const int BM = 128, BN = 128, BK = 8, TM = 8, TN = 8;
    __shared__ float As[BK][BM];
    __shared__ float Bs[BK][BN];

    int tid = threadIdx.x;
    int bm = blockIdx.y * BM;
    int bn = blockIdx.x * BN;
    int tm = (tid >> 4) * TM;   // 0..120
    int tn = (tid & 15) * TN;   // 0..120

    float acc[TM][TN];
#pragma unroll
    for (int i = 0; i < TM; i++)
#pragma unroll
        for (int j = 0; j < TN; j++) acc[i][j] = 0.f;

    int lrow = tid >> 1;          // 0..127
    int lcol = (tid & 1) * 4;     // 0 or 4
    const float* Arow = A + (size_t)(bm + lrow) * K;
    const float* Wrow = W + (size_t)(bn + lrow) * K;

    for (int k0 = 0; k0 < K; k0 += BK) {
#pragma unroll
        for (int i = 0; i < 4; i++) {
            int k = k0 + lcol + i;
            As[lcol + i][lrow] = (k < K) ? Arow[k] : 0.f;
            Bs[lcol + i][lrow] = (k < K) ? Wrow[k] : 0.f;
        }
        __syncthreads();
#pragma unroll
        for (int kk = 0; kk < BK; kk++) {
            float a[TM], b[TN];
#pragma unroll
            for (int i = 0; i < TM; i++) a[i] = As[kk][tm + i];
#pragma unroll
            for (int j = 0; j < TN; j++) b[j] = Bs[kk][tn + j];
#pragma unroll
            for (int i = 0; i < TM; i++)
#pragma unroll
                for (int j = 0; j < TN; j++) acc[i][j] += a[i] * b[j];
        }
        __syncthreads();
    }

#pragma unroll
    for (int i = 0; i < TM; i++) {
        int m = bm + tm + i;
#pragma unroll
        for (int j = 0; j < TN; j++) {
            int n = bn + tn + j;
            float v = acc[i][j] + bias[n];
            if (res) v += res[(size_t)m * N + n];
            if (ACT == 1) v = v > 0.f ? v : 0.f;
            if (ACT == 2) v = v / (1.f + expf(-v));
            C[(size_t)m * N + n] = v;
        }
    }
}

// ---------------- attention: one warp per (node, head) ----------------
__global__ void attn_kernel(const float* __restrict__ qkv,
                            const int* __restrict__ batch,
                            float* __restrict__ o)
{
    __shared__ float ssc[8][MAX_CNT];   // 8 warps per block
    int gw   = (blockIdx.x * blockDim.x + threadIdx.x) >> 5;
    int lane = threadIdx.x & 31;
    int wib  = (threadIdx.x >> 5);
    int node = gw >> 3;
    int head = gw & 7;
    if (node >= N_NODES) return;

    int g  = batch[node];
    int s0 = g_starts[g];
    int cnt = g_counts[g];
    if (cnt > MAX_CNT) cnt = MAX_CNT;

    const float scale = 0.125f;  // 1/sqrt(64)
    const float* qr = qkv + (size_t)node * (3 * DMODEL) + head * HDIM;
    float q0 = qr[lane] * scale;
    float q1 = qr[lane + 32] * scale;

    // pass 1: scores + max
    float mx = -1e30f;
    const float* kbase = qkv + (size_t)s0 * (3 * DMODEL) + DMODEL + head * HDIM;
    for (int j = 0; j < cnt; j++) {
        const float* kr = kbase + (size_t)j * (3 * DMODEL);
        float p = q0 * kr[lane] + q1 * kr[lane + 32];
#pragma unroll
        for (int off = 16; off; off >>= 1)
            p += __shfl_xor_sync(0xffffffffu, p, off);
        if (lane == 0) ssc[wib][j] = p;
        mx = fmaxf(mx, p);
    }
    __syncwarp();

    // pass 2: exp + sum
    float lsum = 0.f;
    for (int idx = lane; idx < cnt; idx += 32) {
        float e = expf(ssc[wib][idx] - mx);
        ssc[wib][idx] = e;
        lsum += e;
    }
#pragma unroll
    for (int off = 16; off; off >>= 1)
        lsum += __shfl_xor_sync(0xffffffffu, lsum, off);
    float inv = 1.f / lsum;
    __syncwarp();

    // pass 3: weighted sum of V
    float a0 = 0.f, a1 = 0.f;
    const float* vbase = qkv + (size_t)s0 * (3 * DMODEL) + 2 * DMODEL + head * HDIM;
    for (int j = 0; j < cnt; j++) {
        float w = ssc[wib][j];
        const float* vr = vbase + (size_t)j * (3 * DMODEL);
        a0 += w * vr[lane];
        a1 += w * vr[lane + 32];
    }
    float* orow = o + (size_t)node * DMODEL + head * HDIM;
    orow[lane]      = a0 * inv;
    orow[lane + 32] = a1 * inv;
}

// ---------------- layernorm (in-place), one warp per row ----------------
__global__ void ln_kernel(float* __restrict__ x,
                          const float* __restrict__ gamma,
                          const float* __restrict__ beta)
{
    int row  = (blockIdx.x * blockDim.x + threadIdx.x) >> 5;
    int lane = threadIdx.x & 31;
    if (row >= N_NODES) return;
    float* xr = x + (size_t)row * DMODEL;

    float v[16];
    float s = 0.f;
#pragma unroll
    for (int i = 0; i < 16; i++) { v[i] = xr[i * 32 + lane]; s += v[i]; }
#pragma unroll
    for (int off = 16; off; off >>= 1) s += __shfl_xor_sync(0xffffffffu, s, off);
    float mu = s * (1.f / DMODEL);

    float s2 = 0.f;
#pragma unroll
    for (int i = 0; i < 16; i++) { float d = v[i] - mu; v[i] = d; s2 += d * d; }
#pragma unroll
    for (int off = 16; off; off >>= 1) s2 += __shfl_xor_sync(0xffffffffu, s2, off);
    float rstd = rsqrtf(s2 * (1.f / DMODEL) + 1e-5f);

#pragma unroll
    for (int i = 0; i < 16; i++) {
        int c = i * 32 + lane;
        xr[c] = v[i] * rstd * gamma[c] + beta[c];
    }
}

// ---------------- segment mean pool: one block per graph ----------------
__global__ void pool_kernel(const float* __restrict__ h, float* __restrict__ pooled)
{
    int g = blockIdx.x;
    int d = threadIdx.x;   // 512 threads
    int s0 = g_starts[g];
    int c  = g_counts[g];
    float acc = 0.f;
    for (int j = 0; j < c; j++) acc += h[(size_t)(s0 + j) * DMODEL + d];
    pooled[g * DMODEL + d] = (c > 0) ? acc / (float)c : 0.f;
}

// ---------------- final head: out[g] = ph[g] . w2 + b2 ----------------
__global__ void head2_kernel(const float* __restrict__ ph,
                             const float* __restrict__ w2,
                             const float* __restrict__ b2,
                             float* __restrict__ out)
{
    int g = blockIdx.x;
    int lane = threadIdx.x;
    float acc = 0.f;
    for (int i = lane; i < DMODEL; i += 32) acc += ph[g * DMODEL + i] * w2[i];
#pragma unroll
    for (int off = 16; off; off >>= 1) acc += __shfl_xor_sync(0xffffffffu, acc, off);
    if (lane == 0) out[g] = acc + b2[0];
}

// ---------------- host orchestration ----------------
extern "C" void kernel_launch(void* const* d_in, const int* in_sizes, int n_in,
                              void* d_out, int out_size)
{
    const float* node_features = (const float*)d_in[0];
    const int*   batch         = (const int*)  d_in[3];   // int32 (JAX x64 off)
    const float* emb_w   = (const float*)d_in[4];
    const float* emb_b   = (const float*)d_in[5];
    const float* in_proj_w = (const float*)d_in[6];
    const float* in_proj_b = (const float*)d_in[7];
    const float* out_w   = (const float*)d_in[8];
    const float* out_b   = (const float*)d_in[9];
    const float* ln1_g   = (const float*)d_in[10];
    const float* ln1_b   = (const float*)d_in[11];
    const float* ffn_w1  = (const float*)d_in[12];
    const float* ffn_b1  = (const float*)d_in[13];
    const float* ffn_w2  = (const float*)d_in[14];
    const float* ffn_b2  = (const float*)d_in[15];
    const float* ln2_g   = (const float*)d_in[16];
    const float* ln2_b   = (const float*)d_in[17];
    const float* head_w1 = (const float*)d_in[18];
    const float* head_b1 = (const float*)d_in[19];
    const float* head_w2 = (const float*)d_in[20];
    const float* head_b2 = (const float*)d_in[21];
    float* out = (float*)d_out;

    float *ph, *pqkv, *po, *px, *pf, *ppool, *pph;
    int *pcounts;
    cudaGetSymbolAddress((void**)&ph,     g_h);
    cudaGetSymbolAddress((void**)&pqkv,   g_qkv);
    cudaGetSymbolAddress((void**)&po,     g_o);
    cudaGetSymbolAddress((void**)&px,     g_x);
    cudaGetSymbolAddress((void**)&pf,     g_f);
    cudaGetSymbolAddress((void**)&ppool,  g_pool);
    cudaGetSymbolAddress((void**)&pph,    g_ph);
    cudaGetSymbolAddress((void**)&pcounts, g_counts);

    // graph metadata
    cudaMemsetAsync(pcounts, 0, B_GRAPHS * sizeof(int));
    count_kernel<<<(N_NODES + 255) / 256, 256>>>(batch);
    scan_kernel<<<1, 1>>>();

    // embedding: h = X @ emb_w^T + emb_b   (24576 x 92 -> 24576 x 512)
    sgemm_kernel<0><<<dim3(DMODEL / 128, N_NODES / 128), 256>>>(
        node_features, emb_w, emb_b, nullptr, ph, N_NODES, DMODEL, D_IN);

    for (int l = 0; l < NLAYER; l++) {
        // qkv = h @ in_proj^T + b
        sgemm_kernel<0><<<dim3(3 * DMODEL / 128, N_NODES / 128), 256>>>(
            ph, in_proj_w + (size_t)l * 3 * DMODEL * DMODEL,
            in_proj_b + (size_t)l * 3 * DMODEL, nullptr, pqkv,
            N_NODES, 3 * DMODEL, DMODEL);

        // per-graph full attention (ragged)
        attn_kernel<<<N_NODES * NHEAD / 8, 256>>>(pqkv, batch, po);

        // x = h + o @ out_w^T + b ; then LN1
        sgemm_kernel<0><<<dim3(DMODEL / 128, N_NODES / 128), 256>>>(
            po, out_w + (size_t)l * DMODEL * DMODEL,
            out_b + (size_t)l * DMODEL, ph, px, N_NODES, DMODEL, DMODEL);
        ln_kernel<<<N_NODES / 8, 256>>>(px, ln1_g + (size_t)l * DMODEL,
                                        ln1_b + (size_t)l * DMODEL);

        // f = relu(x @ w1^T + b1)
        sgemm_kernel<1><<<dim3(DFF / 128, N_NODES / 128), 256>>>(
            px, ffn_w1 + (size_t)l * DFF * DMODEL,
            ffn_b1 + (size_t)l * DFF, nullptr, pf, N_NODES, DFF, DMODEL);

        // h = x + f @ w2^T + b2 ; then LN2
        sgemm_kernel<0><<<dim3(DMODEL / 128, N_NODES / 128), 256>>>(
            pf, ffn_w2 + (size_t)l * DMODEL * DFF,
            ffn_b2 + (size_t)l * DMODEL, px, ph, N_NODES, DMODEL, DFF);
        ln_kernel<<<N_NODES / 8, 256>>>(ph, ln2_g + (size_t)l * DMODEL,
                                        ln2_b + (size_t)l * DMODEL);
    }

    // segment mean pool -> head
    pool_kernel<<<B_GRAPHS, DMODEL>>>(ph, ppool);
    sgemm_kernel<2><<<dim3(DMODEL / 128, B_GRAPHS / 128), 256>>>(
        ppool, head_w1, head_b1, nullptr, pph, B_GRAPHS, DMODEL, DMODEL);
    head2_kernel<<<B_GRAPHS, 32>>>(pph, head_w2, head_b2, out);
}

// round 3
// speedup vs baseline: 1.3380x; 1.3380x over previous
#include <cuda_runtime.h>
#include <math.h>

#define N_NODES 24576
#define B_GRAPHS 128
#define D_IN     92
#define DMODEL   512
#define NHEAD    8
#define HDIM     64
#define NLAYER   3
#define DFF      2048
#define MAX_CNT  512   // safe bound on nodes per graph (mean 192, sd ~14)

// ---------------- device scratch (no allocations allowed) ----------------
__device__ float g_h   [(size_t)N_NODES * DMODEL];      // hidden state
__device__ float g_qkv [(size_t)N_NODES * 3 * DMODEL];  // fused qkv
__device__ float g_o   [(size_t)N_NODES * DMODEL];      // attn concat out
__device__ float g_x   [(size_t)N_NODES * DMODEL];      // post-attn residual
__device__ float g_f   [(size_t)N_NODES * DFF];         // ffn intermediate
__device__ float g_pool[B_GRAPHS * DMODEL];
__device__ float g_ph  [B_GRAPHS * DMODEL];
__device__ int   g_counts[B_GRAPHS];
__device__ int   g_starts[B_GRAPHS];

// ---------------- graph metadata ----------------
__global__ void count_kernel(const int* __restrict__ batch) {
    int i = blockIdx.x * blockDim.x + threadIdx.x;
    if (i < N_NODES) {
        int g = batch[i];
        if (g >= 0 && g < B_GRAPHS) atomicAdd(&g_counts[g], 1);
    }
}

__global__ void scan_kernel() {
    int s = 0;
    for (int g = 0; g < B_GRAPHS; g++) {
        g_starts[g] = s;
        s += g_counts[g];
    }
}

// ---------------- SGEMM:  C = A @ W^T + bias (+res) (+act) ----------------
// A: M x K row-major, W: N x K row-major, C: M x N row-major.
// M % 128 == 0, N % 128 == 0, K % 4 == 0. ACT: 0 none, 1 relu, 2 silu.
// 128x128 tile, BK=16, 256 threads, 8x8 per thread, double-buffered smem,
// LDS.128 fragment loads.
#define BM 128
#define BN 128
#define BKK 16
#define SMPAD 132   // row stride in floats (128+4), keeps 16B alignment

template <int ACT>
__global__ void __launch_bounds__(256)
sgemm_kernel(const float* __restrict__ A, const float* __restrict__ W,
             const float* __restrict__ bias, const float* __restrict__ res,
             float* __restrict__ C, int M, int N, int K)
{
    __shared__ float As[2][BKK][SMPAD];
    __shared__ float Bs[2][BKK][SMPAD];

    const int tid = threadIdx.x;
    const int bm = blockIdx.y * BM;
    const int bn = blockIdx.x * BN;
    const int tm = (tid >> 4) * 8;    // 0..120
    const int tn = (tid & 15) * 8;    // 0..120

    // global-load mapping: 512 float4 per tile, 2 per thread
    const int r0  = tid >> 2;          // 0..63
    const int c40 = (tid & 3);         // 0..3
    const int r1  = r0 + 64;

    float acc[8][8];
#pragma unroll
    for (int i = 0; i < 8; i++)
#pragma unroll
        for (int j = 0; j < 8; j++) acc[i][j] = 0.f;

    const int ntiles = (K + BKK - 1) / BKK;

    // prefetch registers
    float4 pa0, pa1, pb0, pb1;

    auto ldA = [&](int k0, float4& fa0, float4& fa1) {
        int k = k0 + c40 * 4;
        if (k + 3 < K) {
            fa0 = *(const float4*)(A + (size_t)(bm + r0) * K + k);
            fa1 = *(const float4*)(A + (size_t)(bm + r1) * K + k);
        } else {
            fa0 = make_float4(0.f, 0.f, 0.f, 0.f);
            fa1 = make_float4(0.f, 0.f, 0.f, 0.f);
        }
    };
    auto ldB = [&](int k0, float4& fb0, float4& fb1) {
        int k = k0 + c40 * 4;
        if (k + 3 < K) {
            fb0 = *(const float4*)(W + (size_t)(bn + r0) * K + k);
            fb1 = *(const float4*)(W + (size_t)(bn + r1) * K + k);
        } else {
            fb0 = make_float4(0.f, 0.f, 0.f, 0.f);
            fb1 = make_float4(0.f, 0.f, 0.f, 0.f);
        }
    };
    auto stTile = [&](int buf, float4 fa0, float4 fa1, float4 fb0, float4 fb1) {
        int c = c40 * 4;
        As[buf][c + 0][r0] = fa0.x; As[buf][c + 1][r0] = fa0.y;
        As[buf][c + 2][r0] = fa0.z; As[buf][c + 3][r0] = fa0.w;
        As[buf][c + 0][r1] = fa1.x; As[buf][c + 1][r1] = fa1.y;
        As[buf][c + 2][r1] = fa1.z; As[buf][c + 3][r1] = fa1.w;
        Bs[buf][c + 0][r0] = fb0.x; Bs[buf][c + 1][r0] = fb0.y;
        Bs[buf][c + 2][r0] = fb0.z; Bs[buf][c + 3][r0] = fb0.w;
        Bs[buf][c + 0][r1] = fb1.x; Bs[buf][c + 1][r1] = fb1.y;
        Bs[buf][c + 2][r1] = fb1.z; Bs[buf][c + 3][r1] = fb1.w;
    };

    // load tile 0
    ldA(0, pa0, pa1);
    ldB(0, pb0, pb1);
    stTile(0, pa0, pa1, pb0, pb1);
    __syncthreads();

    for (int t = 0; t < ntiles; t++) {
        int buf = t & 1;
        if (t + 1 < ntiles) {
            ldA((t + 1) * BKK, pa0, pa1);
            ldB((t + 1) * BKK, pb0, pb1);
        }
#pragma unroll
        for (int kk = 0; kk < BKK; kk++) {
            float4 a0 = *(const float4*)&As[buf][kk][tm];
            float4 a1 = *(const float4*)&As[buf][kk][tm + 4];
            float4 b0 = *(const float4*)&Bs[buf][kk][tn];
            float4 b1 = *(const float4*)&Bs[buf][kk][tn + 4];
            float a[8] = {a0.x, a0.y, a0.z, a0.w, a1.x, a1.y, a1.z, a1.w};
            float b[8] = {b0.x, b0.y, b0.z, b0.w, b1.x, b1.y, b1.z, b1.w};
#pragma unroll
            for (int i = 0; i < 8; i++)
#pragma unroll
                for (int j = 0; j < 8; j++) acc[i][j] += a[i] * b[j];
        }
        if (t + 1 < ntiles) {
            stTile(1 - buf, pa0, pa1, pb0, pb1);
            __syncthreads();
        }
    }

    // epilogue
    float4 bia0 = *(const float4*)(bias + bn + tn);
    float4 bia1 = *(const float4*)(bias + bn + tn + 4);
    float bi[8] = {bia0.x, bia0.y, bia0.z, bia0.w, bia1.x, bia1.y, bia1.z, bia1.w};
#pragma unroll
    for (int i = 0; i < 8; i++) {
        size_t m = (size_t)(bm + tm + i);
        float v[8];
#pragma unroll
        for (int j = 0; j < 8; j++) v[j] = acc[i][j] + bi[j];
        if (res) {
            float4 rr0 = *(const float4*)(res + m * N + bn + tn);
            float4 rr1 = *(const float4*)(res + m * N + bn + tn + 4);
            v[0] += rr0.x; v[1] += rr0.y; v[2] += rr0.z; v[3] += rr0.w;
            v[4] += rr1.x; v[5] += rr1.y; v[6] += rr1.z; v[7] += rr1.w;
        }
#pragma unroll
        for (int j = 0; j < 8; j++) {
            if (ACT == 1) v[j] = v[j] > 0.f ? v[j] : 0.f;
            if (ACT == 2) v[j] = v[j] / (1.f + expf(-v[j]));
        }
        *(float4*)(C + m * N + bn + tn)     = make_float4(v[0], v[1], v[2], v[3]);
        *(float4*)(C + m * N + bn + tn + 4) = make_float4(v[4], v[5], v[6], v[7]);
    }
}

// ---------------- attention: one warp per (node, head) ----------------
__global__ void attn_kernel(const float* __restrict__ qkv,
                            const int* __restrict__ batch,
                            float* __restrict__ o)
{
    __shared__ float ssc[8][MAX_CNT];   // 8 warps per block
    int gw   = (blockIdx.x * blockDim.x + threadIdx.x) >> 5;
    int lane = threadIdx.x & 31;
    int wib  = (threadIdx.x >> 5);
    int node = gw >> 3;
    int head = gw & 7;
    if (node >= N_NODES) return;

    int g  = batch[node];
    int s0 = g_starts[g];
    int cnt = g_counts[g];
    if (cnt > MAX_CNT) cnt = MAX_CNT;

    const float scale = 0.125f;  // 1/sqrt(64)
    const float* qr = qkv + (size_t)node * (3 * DMODEL) + head * HDIM;
    float q0 = qr[lane] * scale;
    float q1 = qr[lane + 32] * scale;

    // pass 1: scores + max
    float mx = -1e30f;
    const float* kbase = qkv + (size_t)s0 * (3 * DMODEL) + DMODEL + head * HDIM;
    for (int j = 0; j < cnt; j++) {
        const float* kr = kbase + (size_t)j * (3 * DMODEL);
        float p = q0 * kr[lane] + q1 * kr[lane + 32];
#pragma unroll
        for (int off = 16; off; off >>= 1)
            p += __shfl_xor_sync(0xffffffffu, p, off);
        if (lane == 0) ssc[wib][j] = p;
        mx = fmaxf(mx, p);
    }
    __syncwarp();

    // pass 2: exp + sum
    float lsum = 0.f;
    for (int idx = lane; idx < cnt; idx += 32) {
        float e = expf(ssc[wib][idx] - mx);
        ssc[wib][idx] = e;
        lsum += e;
    }
#pragma unroll
    for (int off = 16; off; off >>= 1)
        lsum += __shfl_xor_sync(0xffffffffu, lsum, off);
    float inv = 1.f / lsum;
    __syncwarp();

    // pass 3: weighted sum of V
    float a0 = 0.f, a1 = 0.f;
    const float* vbase = qkv + (size_t)s0 * (3 * DMODEL) + 2 * DMODEL + head * HDIM;
    for (int j = 0; j < cnt; j++) {
        float w = ssc[wib][j];
        const float* vr = vbase + (size_t)j * (3 * DMODEL);
        a0 += w * vr[lane];
        a1 += w * vr[lane + 32];
    }
    float* orow = o + (size_t)node * DMODEL + head * HDIM;
    orow[lane]      = a0 * inv;
    orow[lane + 32] = a1 * inv;
}

// ---------------- layernorm (in-place), one warp per row ----------------
__global__ void ln_kernel(float* __restrict__ x,
                          const float* __restrict__ gamma,
                          const float* __restrict__ beta)
{
    int row  = (blockIdx.x * blockDim.x + threadIdx.x) >> 5;
    int lane = threadIdx.x & 31;
    if (row >= N_NODES) return;
    float* xr = x + (size_t)row * DMODEL;

    float v[16];
    float s = 0.f;
#pragma unroll
    for (int i = 0; i < 16; i++) { v[i] = xr[i * 32 + lane]; s += v[i]; }
#pragma unroll
    for (int off = 16; off; off >>= 1) s += __shfl_xor_sync(0xffffffffu, s, off);
    float mu = s * (1.f / DMODEL);

    float s2 = 0.f;
#pragma unroll
    for (int i = 0; i < 16; i++) { float d = v[i] - mu; v[i] = d; s2 += d * d; }
#pragma unroll
    for (int off = 16; off; off >>= 1) s2 += __shfl_xor_sync(0xffffffffu, s2, off);
    float rstd = rsqrtf(s2 * (1.f / DMODEL) + 1e-5f);

#pragma unroll
    for (int i = 0; i < 16; i++) {
        int c = i * 32 + lane;
        xr[c] = v[i] * rstd * gamma[c] + beta[c];
    }
}

// ---------------- segment mean pool: one block per graph ----------------
__global__ void pool_kernel(const float* __restrict__ h, float* __restrict__ pooled)
{
    int g = blockIdx.x;
    int d = threadIdx.x;   // 512 threads
    int s0 = g_starts[g];
    int c  = g_counts[g];
    float acc = 0.f;
    for (int j = 0; j < c; j++) acc += h[(size_t)(s0 + j) * DMODEL + d];
    pooled[g * DMODEL + d] = (c > 0) ? acc / (float)c : 0.f;
}

// ---------------- final head ----------------
__global__ void head2_kernel(const float* __restrict__ ph,
                             const float* __restrict__ w2,
                             const float* __restrict__ b2,
                             float* __restrict__ out)
{
    int g = blockIdx.x;
    int lane = threadIdx.x;
    float acc = 0.f;
    for (int i = lane; i < DMODEL; i += 32) acc += ph[g * DMODEL + i] * w2[i];
#pragma unroll
    for (int off = 16; off; off >>= 1) acc += __shfl_xor_sync(0xffffffffu, acc, off);
    if (lane == 0) out[g] = acc + b2[0];
}

// ---------------- host orchestration ----------------
extern "C" void kernel_launch(void* const* d_in, const int* in_sizes, int n_in,
                              void* d_out, int out_size)
{
    const float* node_features = (const float*)d_in[0];
    const int*   batch         = (const int*)  d_in[3];   // int32 (JAX x64 off)
    const float* emb_w   = (const float*)d_in[4];
    const float* emb_b   = (const float*)d_in[5];
    const float* in_proj_w = (const float*)d_in[6];
    const float* in_proj_b = (const float*)d_in[7];
    const float* out_w   = (const float*)d_in[8];
    const float* out_b   = (const float*)d_in[9];
    const float* ln1_g   = (const float*)d_in[10];
    const float* ln1_b   = (const float*)d_in[11];
    const float* ffn_w1  = (const float*)d_in[12];
    const float* ffn_b1  = (const float*)d_in[13];
    const float* ffn_w2  = (const float*)d_in[14];
    const float* ffn_b2  = (const float*)d_in[15];
    const float* ln2_g   = (const float*)d_in[16];
    const float* ln2_b   = (const float*)d_in[17];
    const float* head_w1 = (const float*)d_in[18];
    const float* head_b1 = (const float*)d_in[19];
    const float* head_w2 = (const float*)d_in[20];
    const float* head_b2 = (const float*)d_in[21];
    float* out = (float*)d_out;

    float *ph, *pqkv, *po, *px, *pf, *ppool, *pph;
    int *pcounts;
    cudaGetSymbolAddress((void**)&ph,     g_h);
    cudaGetSymbolAddress((void**)&pqkv,   g_qkv);
    cudaGetSymbolAddress((void**)&po,     g_o);
    cudaGetSymbolAddress((void**)&px,     g_x);
    cudaGetSymbolAddress((void**)&pf,     g_f);
    cudaGetSymbolAddress((void**)&ppool,  g_pool);
    cudaGetSymbolAddress((void**)&pph,    g_ph);
    cudaGetSymbolAddress((void**)&pcounts, g_counts);

    // graph metadata
    cudaMemsetAsync(pcounts, 0, B_GRAPHS * sizeof(int));
    count_kernel<<<(N_NODES + 255) / 256, 256>>>(batch);
    scan_kernel<<<1, 1>>>();

    // embedding: h = X @ emb_w^T + emb_b
    sgemm_kernel<0><<<dim3(DMODEL / 128, N_NODES / 128), 256>>>(
        node_features, emb_w, emb_b, nullptr, ph, N_NODES, DMODEL, D_IN);

    for (int l = 0; l < NLAYER; l++) {
        // qkv = h @ in_proj^T + b
        sgemm_kernel<0><<<dim3(3 * DMODEL / 128, N_NODES / 128), 256>>>(
            ph, in_proj_w + (size_t)l * 3 * DMODEL * DMODEL,
            in_proj_b + (size_t)l * 3 * DMODEL, nullptr, pqkv,
            N_NODES, 3 * DMODEL, DMODEL);

        // per-graph full attention (ragged)
        attn_kernel<<<N_NODES * NHEAD / 8, 256>>>(pqkv, batch, po);

        // x = h + o @ out_w^T + b ; then LN1
        sgemm_kernel<0><<<dim3(DMODEL / 128, N_NODES / 128), 256>>>(
            po, out_w + (size_t)l * DMODEL * DMODEL,
            out_b + (size_t)l * DMODEL, ph, px, N_NODES, DMODEL, DMODEL);
        ln_kernel<<<N_NODES / 8, 256>>>(px, ln1_g + (size_t)l * DMODEL,
                                        ln1_b + (size_t)l * DMODEL);

        // f = relu(x @ w1^T + b1)
        sgemm_kernel<1><<<dim3(DFF / 128, N_NODES / 128), 256>>>(
            px, ffn_w1 + (size_t)l * DFF * DMODEL,
            ffn_b1 + (size_t)l * DFF, nullptr, pf, N_NODES, DFF, DMODEL);

        // h = x + f @ w2^T + b2 ; then LN2
        sgemm_kernel<0><<<dim3(DMODEL / 128, N_NODES / 128), 256>>>(
            pf, ffn_w2 + (size_t)l * DMODEL * DFF,
            ffn_b2 + (size_t)l * DMODEL, px, ph, N_NODES, DMODEL, DFF);
        ln_kernel<<<N_NODES / 8, 256>>>(ph, ln2_g + (size_t)l * DMODEL,
                                        ln2_b + (size_t)l * DMODEL);
    }

    // segment mean pool -> head
    pool_kernel<<<B_GRAPHS, DMODEL>>>(ph, ppool);
    sgemm_kernel<2><<<dim3(DMODEL / 128, B_GRAPHS / 128), 256>>>(
        ppool, head_w1, head_b1, nullptr, pph, B_GRAPHS, DMODEL, DMODEL);
    head2_kernel<<<B_GRAPHS, 32>>>(pph, head_w2, head_b2, out);
}

// round 4
// speedup vs baseline: 2.8303x; 2.1154x over previous
#include <cuda_runtime.h>
#include <math.h>
#include <stdint.h>

#define N_NODES 24576
#define B_GRAPHS 128
#define D_IN     92
#define DMODEL   512
#define NHEAD    8
#define HDIM     64
#define NLAYER   3
#define DFF      2048

// ---------------- device scratch (no allocations allowed) ----------------
__device__ float g_h   [(size_t)N_NODES * DMODEL];
__device__ float g_qkv [(size_t)N_NODES * 3 * DMODEL];
__device__ float g_o   [(size_t)N_NODES * DMODEL];
__device__ float g_x   [(size_t)N_NODES * DMODEL];
__device__ float g_f   [(size_t)N_NODES * DFF];
__device__ float g_pool[B_GRAPHS * DMODEL];
__device__ float g_ph  [B_GRAPHS * DMODEL];
__device__ int   g_counts[B_GRAPHS];
__device__ int   g_starts[B_GRAPHS];

// ---------------- graph metadata ----------------
__global__ void count_kernel(const int* __restrict__ batch) {
    int i = blockIdx.x * blockDim.x + threadIdx.x;
    if (i < N_NODES) {
        int g = batch[i];
        if (g >= 0 && g < B_GRAPHS) atomicAdd(&g_counts[g], 1);
    }
}

__global__ void scan_kernel() {
    int s = 0;
    for (int g = 0; g < B_GRAPHS; g++) {
        g_starts[g] = s;
        s += g_counts[g];
    }
}

// ---------------- tf32 helpers ----------------
__device__ __forceinline__ uint32_t f2tf(float x) {
    uint32_t y;
    asm("cvt.rna.tf32.f32 %0, %1;" : "=r"(y) : "f"(x));
    return y;
}

__device__ __forceinline__ void mma_tf32(float d[4], const uint32_t a[4], const uint32_t b[2]) {
    asm volatile(
        "mma.sync.aligned.m16n8k8.row.col.f32.tf32.tf32.f32 "
        "{%0,%1,%2,%3}, {%4,%5,%6,%7}, {%8,%9}, {%0,%1,%2,%3};\n"
        : "+f"(d[0]), "+f"(d[1]), "+f"(d[2]), "+f"(d[3])
        : "r"(a[0]), "r"(a[1]), "r"(a[2]), "r"(a[3]),
          "r"(b[0]), "r"(b[1]));
}

// ---------------- TF32 GEMM:  C = A @ W^T + bias (+res) (+act) ----------------
// A: M x K row-major fp32, W: N x K row-major fp32, C: M x N row-major fp32.
// M % 128 == 0, N % 128 == 0, K % 4 == 0. ACT: 0 none, 1 relu, 2 silu.
// 128x128 block tile, BK=16, 8 warps (2m x 4n), warp tile 64x32, double-buffered.
#define TBM 128
#define TBN 128
#define TBK 16
#define KST 20   // smem row stride in uint32 (16 + 4 pad): conflict-free frag loads

template <int ACT>
__global__ void __launch_bounds__(256, 2)
tgemm_kernel(const float* __restrict__ A, const float* __restrict__ W,
             const float* __restrict__ bias, const float* __restrict__ res,
             float* __restrict__ C, int M, int N, int K)
{
    __shared__ uint32_t As[2][TBM][KST];
    __shared__ uint32_t Bs[2][TBN][KST];

    const int tid  = threadIdx.x;
    const int lane = tid & 31;
    const int wid  = tid >> 5;
    const int mw   = wid >> 2;     // 0..1
    const int nw   = wid & 3;      // 0..3
    const int bm = blockIdx.y * TBM;
    const int bn = blockIdx.x * TBN;
    const int wm = mw * 64;
    const int wn = nw * 32;

    const int r0 = tid >> 2;          // 0..63
    const int c4 = (tid & 3) * 4;     // 0,4,8,12

    float acc[4][4][4];
#pragma unroll
    for (int a = 0; a < 4; a++)
#pragma unroll
        for (int b = 0; b < 4; b++)
#pragma unroll
            for (int c = 0; c < 4; c++) acc[a][b][c] = 0.f;

    const int ntiles = (K + TBK - 1) / TBK;

    uint4 pa0, pa1, pb0, pb1;

    auto ldg4 = [&](const float* __restrict__ P, int row, int k, uint4& o4) {
        if (k + 3 < K) {
            float4 f = *(const float4*)(P + (size_t)row * K + k);
            o4.x = f2tf(f.x); o4.y = f2tf(f.y); o4.z = f2tf(f.z); o4.w = f2tf(f.w);
        } else {
            o4 = make_uint4(0u, 0u, 0u, 0u);
        }
    };

    // prologue: tile 0
    ldg4(A, bm + r0,      c4, pa0);
    ldg4(A, bm + r0 + 64, c4, pa1);
    ldg4(W, bn + r0,      c4, pb0);
    ldg4(W, bn + r0 + 64, c4, pb1);
    *(uint4*)&As[0][r0][c4]      = pa0;
    *(uint4*)&As[0][r0 + 64][c4] = pa1;
    *(uint4*)&Bs[0][r0][c4]      = pb0;
    *(uint4*)&Bs[0][r0 + 64][c4] = pb1;
    __syncthreads();

    const int fr = lane >> 2;   // 0..7
    const int fc = lane & 3;    // 0..3

    for (int t = 0; t < ntiles; t++) {
        int buf = t & 1;
        if (t + 1 < ntiles) {
            int k = (t + 1) * TBK + c4;
            ldg4(A, bm + r0,      k, pa0);
            ldg4(A, bm + r0 + 64, k, pa1);
            ldg4(W, bn + r0,      k, pb0);
            ldg4(W, bn + r0 + 64, k, pb1);
        }
#pragma unroll
        for (int ks = 0; ks < 2; ks++) {
            int kb = ks * 8;
            uint32_t af[4][4], bf[4][2];
#pragma unroll
            for (int mt = 0; mt < 4; mt++) {
                int mrow = wm + mt * 16 + fr;
                af[mt][0] = As[buf][mrow    ][kb + fc];
                af[mt][1] = As[buf][mrow + 8][kb + fc];
                af[mt][2] = As[buf][mrow    ][kb + fc + 4];
                af[mt][3] = As[buf][mrow + 8][kb + fc + 4];
            }
#pragma unroll
            for (int nt = 0; nt < 4; nt++) {
                int nrow = wn + nt * 8 + fr;
                bf[nt][0] = Bs[buf][nrow][kb + fc];
                bf[nt][1] = Bs[buf][nrow][kb + fc + 4];
            }
#pragma unroll
            for (int mt = 0; mt < 4; mt++)
#pragma unroll
                for (int nt = 0; nt < 4; nt++)
                    mma_tf32(acc[mt][nt], af[mt], bf[nt]);
        }
        if (t + 1 < ntiles) {
            int nb = buf ^ 1;
            *(uint4*)&As[nb][r0][c4]      = pa0;
            *(uint4*)&As[nb][r0 + 64][c4] = pa1;
            *(uint4*)&Bs[nb][r0][c4]      = pb0;
            *(uint4*)&Bs[nb][r0 + 64][c4] = pb1;
            __syncthreads();
        }
    }

    // epilogue
#pragma unroll
    for (int mt = 0; mt < 4; mt++) {
#pragma unroll
        for (int nt = 0; nt < 4; nt++) {
            int col = bn + wn + nt * 8 + 2 * fc;
            float2 bi = *(const float2*)(bias + col);
#pragma unroll
            for (int h = 0; h < 2; h++) {
                int row = bm + wm + mt * 16 + fr + h * 8;
                float v0 = acc[mt][nt][h * 2 + 0] + bi.x;
                float v1 = acc[mt][nt][h * 2 + 1] + bi.y;
                if (res) {
                    float2 rr = *(const float2*)(res + (size_t)row * N + col);
                    v0 += rr.x; v1 += rr.y;
                }
                if (ACT == 1) { v0 = fmaxf(v0, 0.f); v1 = fmaxf(v1, 0.f); }
                if (ACT == 2) { v0 = v0 / (1.f + expf(-v0)); v1 = v1 / (1.f + expf(-v1)); }
                *(float2*)(C + (size_t)row * N + col) = make_float2(v0, v1);
            }
        }
    }
}

// ---------------- attention v2: block per (graph, head) ----------------
// 8 query-warps share smem-staged K/V tiles of 32 keys; online softmax.
__global__ void __launch_bounds__(256)
attn2_kernel(const float* __restrict__ qkv, float* __restrict__ o)
{
    __shared__ float Ks[32][65];   // stride 65 -> conflict-free row-per-lane dot
    __shared__ float Vs[32][64];
    __shared__ float qs[8][64];

    const int g = blockIdx.x, head = blockIdx.y;
    const int s0 = g_starts[g], cnt = g_counts[g];
    const int tid = threadIdx.x, lane = tid & 31, wid = tid >> 5;
    const float scale = 0.125f;   // 1/sqrt(64)

    for (int qg = 0; qg < cnt; qg += 8) {
        int ql = qg + wid;
        bool valid = ql < cnt;
        if (valid) {
            const float* qr = qkv + (size_t)(s0 + ql) * (3 * DMODEL) + head * HDIM;
            qs[wid][lane]      = qr[lane] * scale;
            qs[wid][lane + 32] = qr[lane + 32] * scale;
        }
        __syncwarp();

        float m = -1e30f, l = 0.f, a0 = 0.f, a1 = 0.f;

        for (int t0 = 0; t0 < cnt; t0 += 32) {
            int nk = min(32, cnt - t0);
            __syncthreads();
            // stage K/V rows [t0, t0+nk)
            for (int i = tid; i < nk * 16; i += 256) {
                int r = i >> 4, c = (i & 15) * 4;
                const float* kr = qkv + (size_t)(s0 + t0 + r) * (3 * DMODEL) + DMODEL + head * HDIM;
                float4 kf = *(const float4*)(kr + c);
                float4 vf = *(const float4*)(kr + DMODEL + c);
                Ks[r][c] = kf.x; Ks[r][c + 1] = kf.y; Ks[r][c + 2] = kf.z; Ks[r][c + 3] = kf.w;
                *(float4*)&Vs[r][c] = vf;
            }
            __syncthreads();
            if (!valid) continue;

            // lane j = score vs key t0+j
            float s = -1e30f;
            if (lane < nk) {
                float p0 = 0.f, p1 = 0.f, p2 = 0.f, p3 = 0.f;
#pragma unroll 8
                for (int d = 0; d < 64; d += 4) {
                    p0 += qs[wid][d]     * Ks[lane][d];
                    p1 += qs[wid][d + 1] * Ks[lane][d + 1];
                    p2 += qs[wid][d + 2] * Ks[lane][d + 2];
                    p3 += qs[wid][d + 3] * Ks[lane][d + 3];
                }
                s = (p0 + p1) + (p2 + p3);
            }
            float tm = s;
#pragma unroll
            for (int off = 16; off; off >>= 1)
                tm = fmaxf(tm, __shfl_xor_sync(0xffffffffu, tm, off));
            float nm = fmaxf(m, tm);
            float corr = expf(m - nm);
            float e = (lane < nk) ? expf(s - nm) : 0.f;
            float es = e;
#pragma unroll
            for (int off = 16; off; off >>= 1)
                es += __shfl_xor_sync(0xffffffffu, es, off);
            l = l * corr + es;
            a0 *= corr; a1 *= corr;
            for (int j = 0; j < nk; j++) {
                float w = __shfl_sync(0xffffffffu, e, j);
                a0 += w * Vs[j][lane];
                a1 += w * Vs[j][lane + 32];
            }
            m = nm;
        }

        if (valid) {
            float inv = 1.f / l;
            float* orow = o + (size_t)(s0 + ql) * DMODEL + head * HDIM;
            orow[lane]      = a0 * inv;
            orow[lane + 32] = a1 * inv;
        }
    }
}

// ---------------- layernorm (in-place), one warp per row ----------------
__global__ void ln_kernel(float* __restrict__ x,
                          const float* __restrict__ gamma,
                          const float* __restrict__ beta)
{
    int row  = (blockIdx.x * blockDim.x + threadIdx.x) >> 5;
    int lane = threadIdx.x & 31;
    if (row >= N_NODES) return;
    float* xr = x + (size_t)row * DMODEL;

    float v[16];
    float s = 0.f;
#pragma unroll
    for (int i = 0; i < 16; i++) { v[i] = xr[i * 32 + lane]; s += v[i]; }
#pragma unroll
    for (int off = 16; off; off >>= 1) s += __shfl_xor_sync(0xffffffffu, s, off);
    float mu = s * (1.f / DMODEL);

    float s2 = 0.f;
#pragma unroll
    for (int i = 0; i < 16; i++) { float d = v[i] - mu; v[i] = d; s2 += d * d; }
#pragma unroll
    for (int off = 16; off; off >>= 1) s2 += __shfl_xor_sync(0xffffffffu, s2, off);
    float rstd = rsqrtf(s2 * (1.f / DMODEL) + 1e-5f);

#pragma unroll
    for (int i = 0; i < 16; i++) {
        int c = i * 32 + lane;
        xr[c] = v[i] * rstd * gamma[c] + beta[c];
    }
}

// ---------------- segment mean pool: one block per graph ----------------
__global__ void pool_kernel(const float* __restrict__ h, float* __restrict__ pooled)
{
    int g = blockIdx.x;
    int d = threadIdx.x;   // 512 threads
    int s0 = g_starts[g];
    int c  = g_counts[g];
    float acc = 0.f;
    for (int j = 0; j < c; j++) acc += h[(size_t)(s0 + j) * DMODEL + d];
    pooled[g * DMODEL + d] = (c > 0) ? acc / (float)c : 0.f;
}

// ---------------- final head ----------------
__global__ void head2_kernel(const float* __restrict__ ph,
                             const float* __restrict__ w2,
                             const float* __restrict__ b2,
                             float* __restrict__ out)
{
    int g = blockIdx.x;
    int lane = threadIdx.x;
    float acc = 0.f;
    for (int i = lane; i < DMODEL; i += 32) acc += ph[g * DMODEL + i] * w2[i];
#pragma unroll
    for (int off = 16; off; off >>= 1) acc += __shfl_xor_sync(0xffffffffu, acc, off);
    if (lane == 0) out[g] = acc + b2[0];
}

// ---------------- host orchestration ----------------
extern "C" void kernel_launch(void* const* d_in, const int* in_sizes, int n_in,
                              void* d_out, int out_size)
{
    const float* node_features = (const float*)d_in[0];
    const int*   batch         = (const int*)  d_in[3];   // int32 (JAX x64 off)
    const float* emb_w   = (const float*)d_in[4];
    const float* emb_b   = (const float*)d_in[5];
    const float* in_proj_w = (const float*)d_in[6];
    const float* in_proj_b = (const float*)d_in[7];
    const float* out_w   = (const float*)d_in[8];
    const float* out_b   = (const float*)d_in[9];
    const float* ln1_g   = (const float*)d_in[10];
    const float* ln1_b   = (const float*)d_in[11];
    const float* ffn_w1  = (const float*)d_in[12];
    const float* ffn_b1  = (const float*)d_in[13];
    const float* ffn_w2  = (const float*)d_in[14];
    const float* ffn_b2  = (const float*)d_in[15];
    const float* ln2_g   = (const float*)d_in[16];
    const float* ln2_b   = (const float*)d_in[17];
    const float* head_w1 = (const float*)d_in[18];
    const float* head_b1 = (const float*)d_in[19];
    const float* head_w2 = (const float*)d_in[20];
    const float* head_b2 = (const float*)d_in[21];
    float* out = (float*)d_out;

    float *ph, *pqkv, *po, *px, *pf, *ppool, *pph;
    int *pcounts;
    cudaGetSymbolAddress((void**)&ph,     g_h);
    cudaGetSymbolAddress((void**)&pqkv,   g_qkv);
    cudaGetSymbolAddress((void**)&po,     g_o);
    cudaGetSymbolAddress((void**)&px,     g_x);
    cudaGetSymbolAddress((void**)&pf,     g_f);
    cudaGetSymbolAddress((void**)&ppool,  g_pool);
    cudaGetSymbolAddress((void**)&pph,    g_ph);
    cudaGetSymbolAddress((void**)&pcounts, g_counts);

    // graph metadata
    cudaMemsetAsync(pcounts, 0, B_GRAPHS * sizeof(int));
    count_kernel<<<(N_NODES + 255) / 256, 256>>>(batch);
    scan_kernel<<<1, 1>>>();

    // embedding: h = X @ emb_w^T + emb_b
    tgemm_kernel<0><<<dim3(DMODEL / TBN, N_NODES / TBM), 256>>>(
        node_features, emb_w, emb_b, nullptr, ph, N_NODES, DMODEL, D_IN);

    for (int l = 0; l < NLAYER; l++) {
        // qkv = h @ in_proj^T + b
        tgemm_kernel<0><<<dim3(3 * DMODEL / TBN, N_NODES / TBM), 256>>>(
            ph, in_proj_w + (size_t)l * 3 * DMODEL * DMODEL,
            in_proj_b + (size_t)l * 3 * DMODEL, nullptr, pqkv,
            N_NODES, 3 * DMODEL, DMODEL);

        // ragged per-graph attention
        attn2_kernel<<<dim3(B_GRAPHS, NHEAD), 256>>>(pqkv, po);

        // x = h + o @ out_w^T + b ; then LN1
        tgemm_kernel<0><<<dim3(DMODEL / TBN, N_NODES / TBM), 256>>>(
            po, out_w + (size_t)l * DMODEL * DMODEL,
            out_b + (size_t)l * DMODEL, ph, px, N_NODES, DMODEL, DMODEL);
        ln_kernel<<<N_NODES / 8, 256>>>(px, ln1_g + (size_t)l * DMODEL,
                                        ln1_b + (size_t)l * DMODEL);

        // f = relu(x @ w1^T + b1)
        tgemm_kernel<1><<<dim3(DFF / TBN, N_NODES / TBM), 256>>>(
            px, ffn_w1 + (size_t)l * DFF * DMODEL,
            ffn_b1 + (size_t)l * DFF, nullptr, pf, N_NODES, DFF, DMODEL);

        // h = x + f @ w2^T + b2 ; then LN2
        tgemm_kernel<0><<<dim3(DMODEL / TBN, N_NODES / TBM), 256>>>(
            pf, ffn_w2 + (size_t)l * DMODEL * DFF,
            ffn_b2 + (size_t)l * DMODEL, px, ph, N_NODES, DMODEL, DFF);
        ln_kernel<<<N_NODES / 8, 256>>>(ph, ln2_g + (size_t)l * DMODEL,
                                        ln2_b + (size_t)l * DMODEL);
    }

    // segment mean pool -> head
    pool_kernel<<<B_GRAPHS, DMODEL>>>(ph, ppool);
    tgemm_kernel<2><<<dim3(DMODEL / TBN, B_GRAPHS / TBM), 256>>>(
        ppool, head_w1, head_b1, nullptr, pph, B_GRAPHS, DMODEL, DMODEL);
    head2_kernel<<<B_GRAPHS, 32>>>(pph, head_w2, head_b2, out);
}